// round 15
// baseline (speedup 1.0000x reference)
#include <cuda_runtime.h>
#include <cuda_bf16.h>
#include <math.h>
#include <stdint.h>

// Problem constants
#define B_SZ 16
#define L_SZ 4096
#define DM 768
#define NS 32
#define DP 256
#define SCALE 0.0625f  // DP^-0.5 = 1/16

// Output layout: H_hat [B,L,DM] | attn [B,NS,L] | S [B,NS,DM]
#define OFF_ATTN (50331648)             // 16*4096*768
#define OFF_S    (50331648 + 2097152)   // + 16*32*4096

#define NZ 8   // l-split for attnH

typedef unsigned long long u64;

// ---------------------------- f32x2 helpers -----------------------------------
__device__ __forceinline__ u64 pack2(float lo, float hi) {
    u64 r;
    asm("mov.b64 %0, {%1, %2};" : "=l"(r) : "f"(lo), "f"(hi));
    return r;
}
__device__ __forceinline__ void fma2(u64& acc, u64 a, u64 b) {
    asm("fma.rn.f32x2 %0, %1, %2, %0;" : "+l"(acc) : "l"(a), "l"(b));
}
__device__ __forceinline__ float2 unpk2(u64 v) {
    float2 f;
    asm("mov.b64 {%0, %1}, %2;" : "=f"(f.x), "=f"(f.y) : "l"(v));
    return f;
}
__device__ __forceinline__ float red2(u64 v) { float2 f = unpk2(v); return f.x + f.y; }

// ---------------------------- cp.async helpers --------------------------------
__device__ __forceinline__ void cpa16(void* dst_smem, const void* src_gmem) {
    unsigned int d = (unsigned int)__cvta_generic_to_shared(dst_smem);
    asm volatile("cp.async.ca.shared.global [%0], [%1], 16;" :: "r"(d), "l"(src_gmem));
}
#define CPA_COMMIT() asm volatile("cp.async.commit_group;")
#define CPA_WAIT1()  asm volatile("cp.async.wait_group 1;")
#define CPA_WAIT0()  asm volatile("cp.async.wait_group 0;")

// ------------------------- scratch (no allocs allowed) -------------------------
__device__ __align__(16) float g_Q    [NS * DP];             // scale * slots @ Wq^T
__device__ __align__(16) float g_Qh   [NS * DM];             // g_Q @ Wk  (scale folded)
__device__ __align__(16) float g_Wcat [2 * DM * DM];         // rows 0..767: scale*Wrq^T@Wrk; 768..1535: Wrv
__device__ __align__(16) float g_Tp   [NZ][B_SZ * NS * DM];  // partial attn@H
__device__ __align__(16) float g_T    [B_SZ * NS * DM];      // attn@H
__device__ __align__(16) float g_rk2  [B_SZ * NS * DM];      // S @ Mrr^T
__device__ __align__(16) float g_rv   [B_SZ * NS * DM];      // S @ Wrv^T

// ------------------- Q = scale * slots @ Wq^T  [32,256] -----------------------
__global__ void kernel_q(const float* __restrict__ slots, const float* __restrict__ Wq)
{
    __shared__ float s[DM];
    const int k = blockIdx.x;
    const int t = threadIdx.x; // 256
    for (int i = t; i < DM; i += 256) s[i] = slots[k * DM + i];
    __syncthreads();
    const float* w = Wq + (size_t)t * DM;
    float acc = 0.f;
#pragma unroll 4
    for (int d = 0; d < DM; d += 4) {
        float4 wv = *(const float4*)(w + d);
        acc += s[d] * wv.x + s[d + 1] * wv.y + s[d + 2] * wv.z + s[d + 3] * wv.w;
    }
    g_Q[k * DP + t] = acc * SCALE;
}

// ------------------- Qh[k,d] = sum_p Q[k,p] * Wk[p,d]  [32,768] ---------------
__global__ __launch_bounds__(128) void kernel_qh(const float* __restrict__ Wk)
{
    __shared__ float Qk[DP];
    const int k = blockIdx.y;
    const int d = blockIdx.x * 128 + threadIdx.x;
    for (int i = threadIdx.x; i < DP; i += 128) Qk[i] = g_Q[k * DP + i];
    __syncthreads();
    float acc = 0.f;
#pragma unroll 4
    for (int p = 0; p < DP; p++) acc += Qk[p] * Wk[(size_t)p * DM + d];
    g_Qh[k * DM + d] = acc;
}

// -------- Mrr[d,e] = scale * sum_p Wrq[p,d]*Wrk[p,e] -> g_Wcat rows 0..767 ----
__global__ __launch_bounds__(256) void kernel_mrr(
    const float* __restrict__ Wrq, const float* __restrict__ Wrk)
{
    __shared__ __align__(16) float As[16][68];
    __shared__ __align__(16) float Bs[16][68];
    const int t = threadIdx.x;
    const int d0 = blockIdx.y * 64, e0 = blockIdx.x * 64;
    const int tx = t & 15, ty = t >> 4;

    u64 acc2[4][2];
#pragma unroll
    for (int i = 0; i < 4; i++) { acc2[i][0] = 0ull; acc2[i][1] = 0ull; }

    for (int p0 = 0; p0 < DP; p0 += 16) {
        __syncthreads();
#pragma unroll
        for (int it = 0; it < 4; it++) {
            int i = t + it * 256;
            int r = i >> 6, c = i & 63;
            As[r][c] = Wrq[(size_t)(p0 + r) * DM + d0 + c];
            Bs[r][c] = Wrk[(size_t)(p0 + r) * DM + e0 + c];
        }
        __syncthreads();
#pragma unroll
        for (int p = 0; p < 16; p++) {
            float4 a = *(const float4*)&As[p][ty * 4];
            ulonglong2 bv = *(const ulonglong2*)&Bs[p][tx * 4];
            u64 a0 = pack2(a.x, a.x), a1 = pack2(a.y, a.y);
            u64 a2 = pack2(a.z, a.z), a3 = pack2(a.w, a.w);
            fma2(acc2[0][0], a0, bv.x); fma2(acc2[0][1], a0, bv.y);
            fma2(acc2[1][0], a1, bv.x); fma2(acc2[1][1], a1, bv.y);
            fma2(acc2[2][0], a2, bv.x); fma2(acc2[2][1], a2, bv.y);
            fma2(acc2[3][0], a3, bv.x); fma2(acc2[3][1], a3, bv.y);
        }
    }
#pragma unroll
    for (int i = 0; i < 4; i++) {
        float2 lo = unpk2(acc2[i][0]), hi = unpk2(acc2[i][1]);
        float* c = g_Wcat + (size_t)(d0 + ty * 4 + i) * DM + e0 + tx * 4;
        *(float4*)c = make_float4(lo.x * SCALE, lo.y * SCALE, hi.x * SCALE, hi.y * SCALE);
    }
}

// ---------------- 64x64 TN GEMM: C[M,N] = A[M,K] . B[N,K]^T (f32x2) -----------
__global__ __launch_bounds__(256) void gemm64(
    const float* __restrict__ A, const float* __restrict__ Bm,
    float* __restrict__ C, int M, int N, int K)
{
    __shared__ __align__(16) float As[16][68];
    __shared__ __align__(16) float Bs[16][68];
    const int t = threadIdx.x;
    const int bm = blockIdx.y * 64, bn = blockIdx.x * 64;
    const int lr = t >> 2;            // 0..63
    const int lk = (t & 3) << 2;      // 0,4,8,12
    const int tx = t & 15, ty = t >> 4;

    u64 acc2[4][2];
#pragma unroll
    for (int i = 0; i < 4; i++) { acc2[i][0] = 0ull; acc2[i][1] = 0ull; }

    const float* Ap = A + (size_t)(bm + lr) * K + lk;
    const float* Bp = Bm + (size_t)(bn + lr) * K + lk;

    for (int k0 = 0; k0 < K; k0 += 16) {
        float4 a = *(const float4*)(Ap + k0);
        float4 b = *(const float4*)(Bp + k0);
        __syncthreads();
        As[lk + 0][lr] = a.x; As[lk + 1][lr] = a.y;
        As[lk + 2][lr] = a.z; As[lk + 3][lr] = a.w;
        Bs[lk + 0][lr] = b.x; Bs[lk + 1][lr] = b.y;
        Bs[lk + 2][lr] = b.z; Bs[lk + 3][lr] = b.w;
        __syncthreads();
#pragma unroll
        for (int kk = 0; kk < 16; kk++) {
            float4 av = *(const float4*)&As[kk][ty * 4];
            ulonglong2 bv = *(const ulonglong2*)&Bs[kk][tx * 4];
            u64 a0 = pack2(av.x, av.x), a1 = pack2(av.y, av.y);
            u64 a2 = pack2(av.z, av.z), a3 = pack2(av.w, av.w);
            fma2(acc2[0][0], a0, bv.x); fma2(acc2[0][1], a0, bv.y);
            fma2(acc2[1][0], a1, bv.x); fma2(acc2[1][1], a1, bv.y);
            fma2(acc2[2][0], a2, bv.x); fma2(acc2[2][1], a2, bv.y);
            fma2(acc2[3][0], a3, bv.x); fma2(acc2[3][1], a3, bv.y);
        }
    }
#pragma unroll
    for (int i = 0; i < 4; i++) {
        float2 lo = unpk2(acc2[i][0]), hi = unpk2(acc2[i][1]);
        float* c = C + (size_t)(bm + ty * 4 + i) * N + bn + tx * 4;
        *(float4*)c = make_float4(lo.x, lo.y, hi.x, hi.y);
    }
}

// ---- fused dual GEMM: [rk2 | rv] = S @ g_Wcat^T  (N = 1536, split output) ----
__global__ __launch_bounds__(256) void gemm_cat(
    const float* __restrict__ A, float* __restrict__ C1, float* __restrict__ C2)
{
    __shared__ __align__(16) float As[16][68];
    __shared__ __align__(16) float Bs[16][68];
    const int t = threadIdx.x;
    const int bm = blockIdx.y * 64, bn = blockIdx.x * 64;
    const int lr = t >> 2, lk = (t & 3) << 2;
    const int tx = t & 15, ty = t >> 4;

    u64 acc2[4][2];
#pragma unroll
    for (int i = 0; i < 4; i++) { acc2[i][0] = 0ull; acc2[i][1] = 0ull; }

    const float* Ap = A + (size_t)(bm + lr) * DM + lk;
    const float* Bp = g_Wcat + (size_t)(bn + lr) * DM + lk;

    for (int k0 = 0; k0 < DM; k0 += 16) {
        float4 a = *(const float4*)(Ap + k0);
        float4 b = *(const float4*)(Bp + k0);
        __syncthreads();
        As[lk + 0][lr] = a.x; As[lk + 1][lr] = a.y;
        As[lk + 2][lr] = a.z; As[lk + 3][lr] = a.w;
        Bs[lk + 0][lr] = b.x; Bs[lk + 1][lr] = b.y;
        Bs[lk + 2][lr] = b.z; Bs[lk + 3][lr] = b.w;
        __syncthreads();
#pragma unroll
        for (int kk = 0; kk < 16; kk++) {
            float4 av = *(const float4*)&As[kk][ty * 4];
            ulonglong2 bv = *(const ulonglong2*)&Bs[kk][tx * 4];
            u64 a0 = pack2(av.x, av.x), a1 = pack2(av.y, av.y);
            u64 a2 = pack2(av.z, av.z), a3 = pack2(av.w, av.w);
            fma2(acc2[0][0], a0, bv.x); fma2(acc2[0][1], a0, bv.y);
            fma2(acc2[1][0], a1, bv.x); fma2(acc2[1][1], a1, bv.y);
            fma2(acc2[2][0], a2, bv.x); fma2(acc2[2][1], a2, bv.y);
            fma2(acc2[3][0], a3, bv.x); fma2(acc2[3][1], a3, bv.y);
        }
    }
    float* Cd = (bn < DM) ? C1 : C2;
    const int cn = (bn < DM) ? bn : bn - DM;
#pragma unroll
    for (int i = 0; i < 4; i++) {
        float2 lo = unpk2(acc2[i][0]), hi = unpk2(acc2[i][1]);
        float* c = Cd + (size_t)(bm + ty * 4 + i) * DM + cn + tx * 4;
        *(float4*)c = make_float4(lo.x, lo.y, hi.x, hi.y);
    }
}

// ---- streaming logits: 128 threads, 128 tok x 32 slots, 4tok x 8slot/thread --
// 2-stage cp.async pipeline over d-chunks of 32.
#define DCH 32
#define NCH (DM / DCH)   // 24

__global__ __launch_bounds__(128) void kernel_logits2(
    const float* __restrict__ H, float* __restrict__ attn_out)
{
    __shared__ __align__(16) float Hs[2][128][36];
    __shared__ __align__(16) float Qs[2][32][36];
    const int b = blockIdx.y, l0 = blockIdx.x * 128;
    const int t = threadIdx.x;
    const int lane = t & 31, wg = t >> 5;
    const float* Hb = H + ((size_t)b * L_SZ + l0) * DM;

    u64 acc2[4][8];
#pragma unroll
    for (int j = 0; j < 4; j++)
#pragma unroll
        for (int s = 0; s < 8; s++) acc2[j][s] = 0ull;

    auto load_chunk = [&](int ch) {
        const int buf = ch & 1;
        const int d0 = ch * DCH;
#pragma unroll
        for (int it = 0; it < 8; it++) {
            int idx = t + it * 128;
            int r = idx >> 3, c = (idx & 7) << 2;
            cpa16(&Hs[buf][r][c], &Hb[(size_t)r * DM + d0 + c]);
        }
#pragma unroll
        for (int it = 0; it < 2; it++) {
            int idx = t + it * 128;
            int r = idx >> 3, c = (idx & 7) << 2;
            cpa16(&Qs[buf][r][c], &g_Qh[(size_t)r * DM + d0 + c]);
        }
        CPA_COMMIT();
    };

    load_chunk(0);
    for (int ch = 0; ch < NCH; ch++) {
        if (ch + 1 < NCH) { load_chunk(ch + 1); CPA_WAIT1(); }
        else              { CPA_WAIT0(); }
        __syncthreads();
        const int buf = ch & 1;
#pragma unroll
        for (int d = 0; d < DCH; d += 4) {
            ulonglong2 h2[4];
#pragma unroll
            for (int j = 0; j < 4; j++) h2[j] = *(const ulonglong2*)&Hs[buf][lane + 32 * j][d];
#pragma unroll
            for (int s = 0; s < 8; s++) {
                ulonglong2 q2 = *(const ulonglong2*)&Qs[buf][wg * 8 + s][d];
#pragma unroll
                for (int j = 0; j < 4; j++) {
                    fma2(acc2[j][s], h2[j].x, q2.x);
                    fma2(acc2[j][s], h2[j].y, q2.y);
                }
            }
        }
        __syncthreads();
    }
#pragma unroll
    for (int s = 0; s < 8; s++)
#pragma unroll
        for (int j = 0; j < 4; j++)
            attn_out[((size_t)(b * NS + wg * 8 + s)) * L_SZ + l0 + lane + 32 * j] = red2(acc2[j][s]);
}

// ---- fused recon: logits (H . rk2) -> per-token softmax(32) -> mix with rv ---
// 128 threads, 128 tokens per block. Same streaming pipeline; smem reused.
__global__ __launch_bounds__(128) void kernel_recon_full(
    const float* __restrict__ H, float* __restrict__ Hhat)
{
    __shared__ __align__(16) float Hs[2][128][36];
    __shared__ __align__(16) float Qs[2][32][36];
    const int b = blockIdx.y, l0 = blockIdx.x * 128;
    const int t = threadIdx.x;
    const int lane = t & 31, wg = t >> 5;
    const float* Hb = H + ((size_t)b * L_SZ + l0) * DM;
    const float* Bmat = g_rk2 + (size_t)b * NS * DM;

    u64 acc2[4][8];
#pragma unroll
    for (int j = 0; j < 4; j++)
#pragma unroll
        for (int s = 0; s < 8; s++) acc2[j][s] = 0ull;

    auto load_chunk = [&](int ch) {
        const int buf = ch & 1;
        const int d0 = ch * DCH;
#pragma unroll
        for (int it = 0; it < 8; it++) {
            int idx = t + it * 128;
            int r = idx >> 3, c = (idx & 7) << 2;
            cpa16(&Hs[buf][r][c], &Hb[(size_t)r * DM + d0 + c]);
        }
#pragma unroll
        for (int it = 0; it < 2; it++) {
            int idx = t + it * 128;
            int r = idx >> 3, c = (idx & 7) << 2;
            cpa16(&Qs[buf][r][c], &Bmat[(size_t)r * DM + d0 + c]);
        }
        CPA_COMMIT();
    };

    load_chunk(0);
    for (int ch = 0; ch < NCH; ch++) {
        if (ch + 1 < NCH) { load_chunk(ch + 1); CPA_WAIT1(); }
        else              { CPA_WAIT0(); }
        __syncthreads();
        const int buf = ch & 1;
#pragma unroll
        for (int d = 0; d < DCH; d += 4) {
            ulonglong2 h2[4];
#pragma unroll
            for (int j = 0; j < 4; j++) h2[j] = *(const ulonglong2*)&Hs[buf][lane + 32 * j][d];
#pragma unroll
            for (int s = 0; s < 8; s++) {
                ulonglong2 q2 = *(const ulonglong2*)&Qs[buf][wg * 8 + s][d];
#pragma unroll
                for (int j = 0; j < 4; j++) {
                    fma2(acc2[j][s], h2[j].x, q2.x);
                    fma2(acc2[j][s], h2[j].y, q2.y);
                }
            }
        }
        __syncthreads();
    }

    // lg[128][33] and rvs[32][132] alias the (now dead) Hs double buffer.
    // 128*33 + 32*132 = 8448 floats <= 2*128*36 = 9216 floats.
    float (*lg)[33]   = (float(*)[33])(&Hs[0][0][0]);
    float (*rvs)[132] = (float(*)[132])((float*)Hs + 128 * 33);

#pragma unroll
    for (int s = 0; s < 8; s++)
#pragma unroll
        for (int j = 0; j < 4; j++)
            lg[lane + 32 * j][wg * 8 + s] = red2(acc2[j][s]);
    __syncthreads();

    // per-token softmax over 32 slots (thread t <-> token t)
    {
        float m = -1e30f;
#pragma unroll
        for (int k = 0; k < NS; k++) m = fmaxf(m, lg[t][k]);
        float sum = 0.f;
#pragma unroll
        for (int k = 0; k < NS; k++) { float e = __expf(lg[t][k] - m); lg[t][k] = e; sum += e; }
        const float inv = 1.f / sum;
#pragma unroll
        for (int k = 0; k < NS; k++) lg[t][k] *= inv;
    }
    __syncthreads();

    // mix: H_hat[tok, e] = sum_k probs[tok][k] * rv[b,k,e]
    const float* rvb = g_rv + (size_t)b * NS * DM;
    float* Ob = Hhat + ((size_t)b * L_SZ + l0) * DM;

    for (int e0 = 0; e0 < DM; e0 += 128) {
#pragma unroll
        for (int it = 0; it < 8; it++) {
            int idx = t + it * 128;           // 1024 float4: 32 rows x 32 segs
            int r = idx >> 5, c = (idx & 31) << 2;
            *(float4*)&rvs[r][c] = *(const float4*)&rvb[(size_t)r * DM + e0 + c];
        }
        __syncthreads();
#pragma unroll
        for (int tg = 0; tg < 4; tg++) {
            const int tok0 = wg * 32 + tg * 8;
            u64 o2[8][2];
#pragma unroll
            for (int j = 0; j < 8; j++) { o2[j][0] = 0ull; o2[j][1] = 0ull; }
#pragma unroll 2
            for (int k = 0; k < NS; k++) {
                ulonglong2 v = *(const ulonglong2*)&rvs[k][lane * 4];
#pragma unroll
                for (int j = 0; j < 8; j++) {
                    u64 pp = pack2(lg[tok0 + j][k], lg[tok0 + j][k]);
                    fma2(o2[j][0], pp, v.x);
                    fma2(o2[j][1], pp, v.y);
                }
            }
#pragma unroll
            for (int j = 0; j < 8; j++) {
                float2 lo = unpk2(o2[j][0]), hi = unpk2(o2[j][1]);
                *(float4*)&Ob[(size_t)(tok0 + j) * DM + e0 + lane * 4] =
                    make_float4(lo.x, lo.y, hi.x, hi.y);
            }
        }
        __syncthreads();
    }
}

// ----------------- softmax over rows of 4096 (in place, smem row) -------------
__global__ __launch_bounds__(256) void kernel_softmax(float* __restrict__ attn)
{
    __shared__ __align__(16) float row[L_SZ];
    __shared__ float red[256];
    float* p = attn + (size_t)blockIdx.x * L_SZ;
    const int t = threadIdx.x;

    float m = -1e30f;
#pragma unroll
    for (int i = t * 4; i < L_SZ; i += 1024) {
        float4 v = *(const float4*)(p + i);
        *(float4*)&row[i] = v;
        m = fmaxf(m, fmaxf(fmaxf(v.x, v.y), fmaxf(v.z, v.w)));
    }
    red[t] = m; __syncthreads();
    for (int s = 128; s > 0; s >>= 1) { if (t < s) red[t] = fmaxf(red[t], red[t + s]); __syncthreads(); }
    m = red[0]; __syncthreads();

    float sum = 0.f;
#pragma unroll
    for (int i = t * 4; i < L_SZ; i += 1024) {
        float4 v = *(const float4*)&row[i];
        v.x = __expf(v.x - m); v.y = __expf(v.y - m);
        v.z = __expf(v.z - m); v.w = __expf(v.w - m);
        *(float4*)&row[i] = v;
        sum += v.x + v.y + v.z + v.w;
    }
    red[t] = sum; __syncthreads();
    for (int s = 128; s > 0; s >>= 1) { if (t < s) red[t] += red[t + s]; __syncthreads(); }
    const float inv = 1.f / red[0];
    __syncthreads();
#pragma unroll
    for (int i = t * 4; i < L_SZ; i += 1024) {
        float4 v = *(const float4*)&row[i];
        *(float4*)(p + i) = make_float4(v.x * inv, v.y * inv, v.z * inv, v.w * inv);
    }
}

// ------------------- T = attn @ H  (partials over NZ l chunks, f32x2) ---------
// 8-row unroll: 8 LDG.128 in flight per warp iteration.
__global__ __launch_bounds__(256) void kernel_attnH(
    const float* __restrict__ attn, const float* __restrict__ H)
{
    __shared__ __align__(16) float as[32][132];
    const int b = blockIdx.y, e0 = blockIdx.x * 128, z = blockIdx.z;
    const int t = threadIdx.x, lane = t & 31, wg = t >> 5;

    u64 acc2[4][2];
#pragma unroll
    for (int i = 0; i < 4; i++) { acc2[i][0] = 0ull; acc2[i][1] = 0ull; }

    const float* Ab = attn + (size_t)b * NS * L_SZ;
    const float* Hb = H + (size_t)b * L_SZ * DM + e0 + lane * 4;
    const int lbeg = z * (L_SZ / NZ);

    for (int l0 = lbeg; l0 < lbeg + (L_SZ / NZ); l0 += 128) {
        __syncthreads();
#pragma unroll
        for (int it = 0; it < 4; it++) {
            int idx = t + it * 256;           // 1024 float4 slots
            int s = idx >> 5, c = (idx & 31) << 2;
            *(float4*)&as[s][c] = *(const float4*)&Ab[(size_t)s * L_SZ + l0 + c];
        }
        __syncthreads();
#pragma unroll 2
        for (int l = 0; l < 128; l += 8) {
            ulonglong2 h2[8];
#pragma unroll
            for (int j = 0; j < 8; j++)
                h2[j] = *(const ulonglong2*)&Hb[(size_t)(l0 + l + j) * DM];
#pragma unroll
            for (int i = 0; i < 4; i++) {
                float4 a  = *(const float4*)&as[wg * 4 + i][l];
                float4 a2 = *(const float4*)&as[wg * 4 + i][l + 4];
                u64 p0 = pack2(a.x, a.x),  p1 = pack2(a.y, a.y);
                u64 p2 = pack2(a.z, a.z),  p3 = pack2(a.w, a.w);
                u64 p4 = pack2(a2.x, a2.x), p5 = pack2(a2.y, a2.y);
                u64 p6 = pack2(a2.z, a2.z), p7 = pack2(a2.w, a2.w);
                fma2(acc2[i][0], p0, h2[0].x); fma2(acc2[i][1], p0, h2[0].y);
                fma2(acc2[i][0], p1, h2[1].x); fma2(acc2[i][1], p1, h2[1].y);
                fma2(acc2[i][0], p2, h2[2].x); fma2(acc2[i][1], p2, h2[2].y);
                fma2(acc2[i][0], p3, h2[3].x); fma2(acc2[i][1], p3, h2[3].y);
                fma2(acc2[i][0], p4, h2[4].x); fma2(acc2[i][1], p4, h2[4].y);
                fma2(acc2[i][0], p5, h2[5].x); fma2(acc2[i][1], p5, h2[5].y);
                fma2(acc2[i][0], p6, h2[6].x); fma2(acc2[i][1], p6, h2[6].y);
                fma2(acc2[i][0], p7, h2[7].x); fma2(acc2[i][1], p7, h2[7].y);
            }
        }
    }
#pragma unroll
    for (int i = 0; i < 4; i++) {
        float2 lo = unpk2(acc2[i][0]), hi = unpk2(acc2[i][1]);
        *(float4*)&g_Tp[z][((size_t)b * NS + wg * 4 + i) * DM + e0 + lane * 4] =
            make_float4(lo.x, lo.y, hi.x, hi.y);
    }
}

__global__ void kernel_reduceT()
{
    const int i = blockIdx.x * 256 + threadIdx.x;
    if (i < B_SZ * NS * DM) {
        float s = 0.f;
#pragma unroll
        for (int z = 0; z < NZ; z++) s += g_Tp[z][i];
        g_T[i] = s;
    }
}

// ------------------------------- launcher -------------------------------------
extern "C" void kernel_launch(void* const* d_in, const int* in_sizes, int n_in,
                              void* d_out, int out_size)
{
    const float* H     = (const float*)d_in[0];
    // d_in[1] = mask (all true) — unused
    const float* slots = (const float*)d_in[2];
    const float* Wq    = (const float*)d_in[3];
    const float* Wk    = (const float*)d_in[4];
    const float* Wv    = (const float*)d_in[5];
    const float* Wrq   = (const float*)d_in[6];
    const float* Wrk   = (const float*)d_in[7];
    const float* Wrv   = (const float*)d_in[8];

    float* out      = (float*)d_out;
    float* out_Hhat = out;
    float* out_attn = out + OFF_ATTN;
    float* out_S    = out + OFF_S;

    float *pT, *pWcat, *prk2, *prv;
    cudaGetSymbolAddress((void**)&pT,    g_T);
    cudaGetSymbolAddress((void**)&pWcat, g_Wcat);
    cudaGetSymbolAddress((void**)&prk2,  g_rk2);
    cudaGetSymbolAddress((void**)&prv,   g_rv);

    // tiny precomputes
    kernel_q<<<NS, 256>>>(slots, Wq);
    kernel_qh<<<dim3(DM / 128, NS), 128>>>(Wk);
    kernel_mrr<<<dim3(DM / 64, DM / 64), 256>>>(Wrq, Wrk);
    // Wrv -> upper half of g_Wcat (D2D async copy, graph-capturable)
    cudaMemcpyAsync(pWcat + (size_t)DM * DM, Wrv, (size_t)DM * DM * sizeof(float),
                    cudaMemcpyDeviceToDevice, 0);

    // pass1: logits + softmax -> attn (output)
    kernel_logits2<<<dim3(L_SZ / 128, B_SZ), 128>>>(H, out_attn);
    kernel_softmax<<<B_SZ * NS, 256>>>(out_attn);

    // pass2: T = attn @ H
    kernel_attnH<<<dim3(DM / 128, B_SZ, NZ), 256>>>(out_attn, H);
    kernel_reduceT<<<(B_SZ * NS * DM + 255) / 256, 256>>>();

    // small GEMMs: S = T@Wv^T (output), then [rk2|rv] = S @ Wcat^T (fused)
    gemm64<<<dim3(DM / 64, (B_SZ * NS) / 64), 256>>>(pT, Wv, out_S, B_SZ * NS, DM, DM);
    gemm_cat<<<dim3(2 * DM / 64, (B_SZ * NS) / 64), 256>>>(out_S, prk2, prv);

    // pass3: fused recon logits + softmax + mix -> H_hat (output)
    kernel_recon_full<<<dim3(L_SZ / 128, B_SZ), 128>>>(H, out_Hhat);
}

// round 16
// speedup vs baseline: 1.4902x; 1.4902x over previous
#include <cuda_runtime.h>
#include <cuda_bf16.h>
#include <math.h>
#include <stdint.h>

// Problem constants
#define B_SZ 16
#define L_SZ 4096
#define DM 768
#define NS 32
#define DP 256
#define SCALE 0.0625f  // DP^-0.5 = 1/16

// Output layout: H_hat [B,L,DM] | attn [B,NS,L] | S [B,NS,DM]
#define OFF_ATTN (50331648)             // 16*4096*768
#define OFF_S    (50331648 + 2097152)   // + 16*32*4096

#define NZ 8   // l-split for attnH

typedef unsigned long long u64;

// ---------------------------- f32x2 helpers -----------------------------------
__device__ __forceinline__ u64 pack2(float lo, float hi) {
    u64 r;
    asm("mov.b64 %0, {%1, %2};" : "=l"(r) : "f"(lo), "f"(hi));
    return r;
}
__device__ __forceinline__ void fma2(u64& acc, u64 a, u64 b) {
    asm("fma.rn.f32x2 %0, %1, %2, %0;" : "+l"(acc) : "l"(a), "l"(b));
}
__device__ __forceinline__ float2 unpk2(u64 v) {
    float2 f;
    asm("mov.b64 {%0, %1}, %2;" : "=f"(f.x), "=f"(f.y) : "l"(v));
    return f;
}
__device__ __forceinline__ float red2(u64 v) { float2 f = unpk2(v); return f.x + f.y; }

// ---------------------------- cp.async helpers --------------------------------
__device__ __forceinline__ void cpa16(void* dst_smem, const void* src_gmem) {
    unsigned int d = (unsigned int)__cvta_generic_to_shared(dst_smem);
    asm volatile("cp.async.ca.shared.global [%0], [%1], 16;" :: "r"(d), "l"(src_gmem));
}
#define CPA_COMMIT() asm volatile("cp.async.commit_group;")
#define CPA_WAIT1()  asm volatile("cp.async.wait_group 1;")
#define CPA_WAIT0()  asm volatile("cp.async.wait_group 0;")

// ------------------------- scratch (no allocs allowed) -------------------------
__device__ __align__(16) float g_Q    [NS * DP];             // scale * slots @ Wq^T
__device__ __align__(16) float g_Qh   [NS * DM];             // g_Q @ Wk  (scale folded)
__device__ __align__(16) float g_Wcat [2 * DM * DM];         // rows 0..767: scale*Wrq^T@Wrk; 768..1535: Wrv
__device__ __align__(16) float g_Tp   [NZ][B_SZ * NS * DM];  // partial attn@H
__device__ __align__(16) float g_T    [B_SZ * NS * DM];      // attn@H
__device__ __align__(16) float g_rk2  [B_SZ * NS * DM];      // S @ Mrr^T
__device__ __align__(16) float g_rv   [B_SZ * NS * DM];      // S @ Wrv^T

// ------------------- Q = scale * slots @ Wq^T  [32,256] -----------------------
__global__ void kernel_q(const float* __restrict__ slots, const float* __restrict__ Wq)
{
    __shared__ float s[DM];
    const int k = blockIdx.x;
    const int t = threadIdx.x; // 256
    for (int i = t; i < DM; i += 256) s[i] = slots[k * DM + i];
    __syncthreads();
    const float* w = Wq + (size_t)t * DM;
    float acc = 0.f;
#pragma unroll 4
    for (int d = 0; d < DM; d += 4) {
        float4 wv = *(const float4*)(w + d);
        acc += s[d] * wv.x + s[d + 1] * wv.y + s[d + 2] * wv.z + s[d + 3] * wv.w;
    }
    g_Q[k * DP + t] = acc * SCALE;
}

// ------------------- Qh[k,d] = sum_p Q[k,p] * Wk[p,d]  [32,768] ---------------
__global__ __launch_bounds__(128) void kernel_qh(const float* __restrict__ Wk)
{
    __shared__ float Qk[DP];
    const int k = blockIdx.y;
    const int d = blockIdx.x * 128 + threadIdx.x;
    for (int i = threadIdx.x; i < DP; i += 128) Qk[i] = g_Q[k * DP + i];
    __syncthreads();
    float acc = 0.f;
#pragma unroll 4
    for (int p = 0; p < DP; p++) acc += Qk[p] * Wk[(size_t)p * DM + d];
    g_Qh[k * DM + d] = acc;
}

// -------- Mrr[d,e] = scale * sum_p Wrq[p,d]*Wrk[p,e] -> g_Wcat rows 0..767 ----
__global__ __launch_bounds__(256) void kernel_mrr(
    const float* __restrict__ Wrq, const float* __restrict__ Wrk)
{
    __shared__ __align__(16) float As[16][68];
    __shared__ __align__(16) float Bs[16][68];
    const int t = threadIdx.x;
    const int d0 = blockIdx.y * 64, e0 = blockIdx.x * 64;
    const int tx = t & 15, ty = t >> 4;

    u64 acc2[4][2];
#pragma unroll
    for (int i = 0; i < 4; i++) { acc2[i][0] = 0ull; acc2[i][1] = 0ull; }

    for (int p0 = 0; p0 < DP; p0 += 16) {
        __syncthreads();
#pragma unroll
        for (int it = 0; it < 4; it++) {
            int i = t + it * 256;
            int r = i >> 6, c = i & 63;
            As[r][c] = Wrq[(size_t)(p0 + r) * DM + d0 + c];
            Bs[r][c] = Wrk[(size_t)(p0 + r) * DM + e0 + c];
        }
        __syncthreads();
#pragma unroll
        for (int p = 0; p < 16; p++) {
            float4 a = *(const float4*)&As[p][ty * 4];
            ulonglong2 bv = *(const ulonglong2*)&Bs[p][tx * 4];
            u64 a0 = pack2(a.x, a.x), a1 = pack2(a.y, a.y);
            u64 a2 = pack2(a.z, a.z), a3 = pack2(a.w, a.w);
            fma2(acc2[0][0], a0, bv.x); fma2(acc2[0][1], a0, bv.y);
            fma2(acc2[1][0], a1, bv.x); fma2(acc2[1][1], a1, bv.y);
            fma2(acc2[2][0], a2, bv.x); fma2(acc2[2][1], a2, bv.y);
            fma2(acc2[3][0], a3, bv.x); fma2(acc2[3][1], a3, bv.y);
        }
    }
#pragma unroll
    for (int i = 0; i < 4; i++) {
        float2 lo = unpk2(acc2[i][0]), hi = unpk2(acc2[i][1]);
        float* c = g_Wcat + (size_t)(d0 + ty * 4 + i) * DM + e0 + tx * 4;
        *(float4*)c = make_float4(lo.x * SCALE, lo.y * SCALE, hi.x * SCALE, hi.y * SCALE);
    }
}

// ---------------- 64x64 TN GEMM: C[M,N] = A[M,K] . B[N,K]^T (f32x2) -----------
__global__ __launch_bounds__(256) void gemm64(
    const float* __restrict__ A, const float* __restrict__ Bm,
    float* __restrict__ C, int M, int N, int K)
{
    __shared__ __align__(16) float As[16][68];
    __shared__ __align__(16) float Bs[16][68];
    const int t = threadIdx.x;
    const int bm = blockIdx.y * 64, bn = blockIdx.x * 64;
    const int lr = t >> 2;            // 0..63
    const int lk = (t & 3) << 2;      // 0,4,8,12
    const int tx = t & 15, ty = t >> 4;

    u64 acc2[4][2];
#pragma unroll
    for (int i = 0; i < 4; i++) { acc2[i][0] = 0ull; acc2[i][1] = 0ull; }

    const float* Ap = A + (size_t)(bm + lr) * K + lk;
    const float* Bp = Bm + (size_t)(bn + lr) * K + lk;

    for (int k0 = 0; k0 < K; k0 += 16) {
        float4 a = *(const float4*)(Ap + k0);
        float4 b = *(const float4*)(Bp + k0);
        __syncthreads();
        As[lk + 0][lr] = a.x; As[lk + 1][lr] = a.y;
        As[lk + 2][lr] = a.z; As[lk + 3][lr] = a.w;
        Bs[lk + 0][lr] = b.x; Bs[lk + 1][lr] = b.y;
        Bs[lk + 2][lr] = b.z; Bs[lk + 3][lr] = b.w;
        __syncthreads();
#pragma unroll
        for (int kk = 0; kk < 16; kk++) {
            float4 av = *(const float4*)&As[kk][ty * 4];
            ulonglong2 bv = *(const ulonglong2*)&Bs[kk][tx * 4];
            u64 a0 = pack2(av.x, av.x), a1 = pack2(av.y, av.y);
            u64 a2 = pack2(av.z, av.z), a3 = pack2(av.w, av.w);
            fma2(acc2[0][0], a0, bv.x); fma2(acc2[0][1], a0, bv.y);
            fma2(acc2[1][0], a1, bv.x); fma2(acc2[1][1], a1, bv.y);
            fma2(acc2[2][0], a2, bv.x); fma2(acc2[2][1], a2, bv.y);
            fma2(acc2[3][0], a3, bv.x); fma2(acc2[3][1], a3, bv.y);
        }
    }
#pragma unroll
    for (int i = 0; i < 4; i++) {
        float2 lo = unpk2(acc2[i][0]), hi = unpk2(acc2[i][1]);
        float* c = C + (size_t)(bm + ty * 4 + i) * N + bn + tx * 4;
        *(float4*)c = make_float4(lo.x, lo.y, hi.x, hi.y);
    }
}

// ---- fused dual GEMM: [rk2 | rv] = S @ g_Wcat^T  (N = 1536, split output) ----
__global__ __launch_bounds__(256) void gemm_cat(
    const float* __restrict__ A, float* __restrict__ C1, float* __restrict__ C2)
{
    __shared__ __align__(16) float As[16][68];
    __shared__ __align__(16) float Bs[16][68];
    const int t = threadIdx.x;
    const int bm = blockIdx.y * 64, bn = blockIdx.x * 64;
    const int lr = t >> 2, lk = (t & 3) << 2;
    const int tx = t & 15, ty = t >> 4;

    u64 acc2[4][2];
#pragma unroll
    for (int i = 0; i < 4; i++) { acc2[i][0] = 0ull; acc2[i][1] = 0ull; }

    const float* Ap = A + (size_t)(bm + lr) * DM + lk;
    const float* Bp = g_Wcat + (size_t)(bn + lr) * DM + lk;

    for (int k0 = 0; k0 < DM; k0 += 16) {
        float4 a = *(const float4*)(Ap + k0);
        float4 b = *(const float4*)(Bp + k0);
        __syncthreads();
        As[lk + 0][lr] = a.x; As[lk + 1][lr] = a.y;
        As[lk + 2][lr] = a.z; As[lk + 3][lr] = a.w;
        Bs[lk + 0][lr] = b.x; Bs[lk + 1][lr] = b.y;
        Bs[lk + 2][lr] = b.z; Bs[lk + 3][lr] = b.w;
        __syncthreads();
#pragma unroll
        for (int kk = 0; kk < 16; kk++) {
            float4 av = *(const float4*)&As[kk][ty * 4];
            ulonglong2 bv = *(const ulonglong2*)&Bs[kk][tx * 4];
            u64 a0 = pack2(av.x, av.x), a1 = pack2(av.y, av.y);
            u64 a2 = pack2(av.z, av.z), a3 = pack2(av.w, av.w);
            fma2(acc2[0][0], a0, bv.x); fma2(acc2[0][1], a0, bv.y);
            fma2(acc2[1][0], a1, bv.x); fma2(acc2[1][1], a1, bv.y);
            fma2(acc2[2][0], a2, bv.x); fma2(acc2[2][1], a2, bv.y);
            fma2(acc2[3][0], a3, bv.x); fma2(acc2[3][1], a3, bv.y);
        }
    }
    float* Cd = (bn < DM) ? C1 : C2;
    const int cn = (bn < DM) ? bn : bn - DM;
#pragma unroll
    for (int i = 0; i < 4; i++) {
        float2 lo = unpk2(acc2[i][0]), hi = unpk2(acc2[i][1]);
        float* c = Cd + (size_t)(bm + ty * 4 + i) * DM + cn + tx * 4;
        *(float4*)c = make_float4(lo.x, lo.y, hi.x, hi.y);
    }
}

// ---- streaming logits: 128 threads, 128 tok x 32 slots, 4tok x 8slot/thread --
// 2-stage cp.async pipeline over d-chunks of 32.
#define DCH 32
#define NCH (DM / DCH)   // 24

__global__ __launch_bounds__(128) void kernel_logits2(
    const float* __restrict__ H, float* __restrict__ attn_out)
{
    __shared__ __align__(16) float Hs[2][128][36];
    __shared__ __align__(16) float Qs[2][32][36];
    const int b = blockIdx.y, l0 = blockIdx.x * 128;
    const int t = threadIdx.x;
    const int lane = t & 31, wg = t >> 5;
    const float* Hb = H + ((size_t)b * L_SZ + l0) * DM;

    u64 acc2[4][8];
#pragma unroll
    for (int j = 0; j < 4; j++)
#pragma unroll
        for (int s = 0; s < 8; s++) acc2[j][s] = 0ull;

    auto load_chunk = [&](int ch) {
        const int buf = ch & 1;
        const int d0 = ch * DCH;
#pragma unroll
        for (int it = 0; it < 8; it++) {
            int idx = t + it * 128;
            int r = idx >> 3, c = (idx & 7) << 2;
            cpa16(&Hs[buf][r][c], &Hb[(size_t)r * DM + d0 + c]);
        }
#pragma unroll
        for (int it = 0; it < 2; it++) {
            int idx = t + it * 128;
            int r = idx >> 3, c = (idx & 7) << 2;
            cpa16(&Qs[buf][r][c], &g_Qh[(size_t)r * DM + d0 + c]);
        }
        CPA_COMMIT();
    };

    load_chunk(0);
    for (int ch = 0; ch < NCH; ch++) {
        if (ch + 1 < NCH) { load_chunk(ch + 1); CPA_WAIT1(); }
        else              { CPA_WAIT0(); }
        __syncthreads();
        const int buf = ch & 1;
#pragma unroll
        for (int d = 0; d < DCH; d += 4) {
            ulonglong2 h2[4];
#pragma unroll
            for (int j = 0; j < 4; j++) h2[j] = *(const ulonglong2*)&Hs[buf][lane + 32 * j][d];
#pragma unroll
            for (int s = 0; s < 8; s++) {
                ulonglong2 q2 = *(const ulonglong2*)&Qs[buf][wg * 8 + s][d];
#pragma unroll
                for (int j = 0; j < 4; j++) {
                    fma2(acc2[j][s], h2[j].x, q2.x);
                    fma2(acc2[j][s], h2[j].y, q2.y);
                }
            }
        }
        __syncthreads();
    }
#pragma unroll
    for (int s = 0; s < 8; s++)
#pragma unroll
        for (int j = 0; j < 4; j++)
            attn_out[((size_t)(b * NS + wg * 8 + s)) * L_SZ + l0 + lane + 32 * j] = red2(acc2[j][s]);
}

// ---- fused recon: logits (H . rk2) -> per-token softmax(32) -> mix with rv ---
// 128 threads, 128 tokens per block. Same streaming pipeline; smem reused.
__global__ __launch_bounds__(128) void kernel_recon_full(
    const float* __restrict__ H, float* __restrict__ Hhat)
{
    __shared__ __align__(16) float Hs[2][128][36];
    __shared__ __align__(16) float Qs[2][32][36];
    const int b = blockIdx.y, l0 = blockIdx.x * 128;
    const int t = threadIdx.x;
    const int lane = t & 31, wg = t >> 5;
    const float* Hb = H + ((size_t)b * L_SZ + l0) * DM;
    const float* Bmat = g_rk2 + (size_t)b * NS * DM;

    u64 acc2[4][8];
#pragma unroll
    for (int j = 0; j < 4; j++)
#pragma unroll
        for (int s = 0; s < 8; s++) acc2[j][s] = 0ull;

    auto load_chunk = [&](int ch) {
        const int buf = ch & 1;
        const int d0 = ch * DCH;
#pragma unroll
        for (int it = 0; it < 8; it++) {
            int idx = t + it * 128;
            int r = idx >> 3, c = (idx & 7) << 2;
            cpa16(&Hs[buf][r][c], &Hb[(size_t)r * DM + d0 + c]);
        }
#pragma unroll
        for (int it = 0; it < 2; it++) {
            int idx = t + it * 128;
            int r = idx >> 3, c = (idx & 7) << 2;
            cpa16(&Qs[buf][r][c], &Bmat[(size_t)r * DM + d0 + c]);
        }
        CPA_COMMIT();
    };

    load_chunk(0);
    for (int ch = 0; ch < NCH; ch++) {
        if (ch + 1 < NCH) { load_chunk(ch + 1); CPA_WAIT1(); }
        else              { CPA_WAIT0(); }
        __syncthreads();
        const int buf = ch & 1;
#pragma unroll
        for (int d = 0; d < DCH; d += 4) {
            ulonglong2 h2[4];
#pragma unroll
            for (int j = 0; j < 4; j++) h2[j] = *(const ulonglong2*)&Hs[buf][lane + 32 * j][d];
#pragma unroll
            for (int s = 0; s < 8; s++) {
                ulonglong2 q2 = *(const ulonglong2*)&Qs[buf][wg * 8 + s][d];
#pragma unroll
                for (int j = 0; j < 4; j++) {
                    fma2(acc2[j][s], h2[j].x, q2.x);
                    fma2(acc2[j][s], h2[j].y, q2.y);
                }
            }
        }
        __syncthreads();
    }

    // lg[128][33] and rvs[32][132] alias the (now dead) Hs double buffer.
    // 128*33 + 32*132 = 8448 floats <= 2*128*36 = 9216 floats.
    float (*lg)[33]   = (float(*)[33])(&Hs[0][0][0]);
    float (*rvs)[132] = (float(*)[132])((float*)Hs + 128 * 33);

#pragma unroll
    for (int s = 0; s < 8; s++)
#pragma unroll
        for (int j = 0; j < 4; j++)
            lg[lane + 32 * j][wg * 8 + s] = red2(acc2[j][s]);
    __syncthreads();

    // per-token softmax over 32 slots (thread t <-> token t)
    {
        float m = -1e30f;
#pragma unroll
        for (int k = 0; k < NS; k++) m = fmaxf(m, lg[t][k]);
        float sum = 0.f;
#pragma unroll
        for (int k = 0; k < NS; k++) { float e = __expf(lg[t][k] - m); lg[t][k] = e; sum += e; }
        const float inv = 1.f / sum;
#pragma unroll
        for (int k = 0; k < NS; k++) lg[t][k] *= inv;
    }
    __syncthreads();

    // mix: H_hat[tok, e] = sum_k probs[tok][k] * rv[b,k,e]
    const float* rvb = g_rv + (size_t)b * NS * DM;
    float* Ob = Hhat + ((size_t)b * L_SZ + l0) * DM;

    for (int e0 = 0; e0 < DM; e0 += 128) {
#pragma unroll
        for (int it = 0; it < 8; it++) {
            int idx = t + it * 128;           // 1024 float4: 32 rows x 32 segs
            int r = idx >> 5, c = (idx & 31) << 2;
            *(float4*)&rvs[r][c] = *(const float4*)&rvb[(size_t)r * DM + e0 + c];
        }
        __syncthreads();
#pragma unroll
        for (int tg = 0; tg < 4; tg++) {
            const int tok0 = wg * 32 + tg * 8;
            u64 o2[8][2];
#pragma unroll
            for (int j = 0; j < 8; j++) { o2[j][0] = 0ull; o2[j][1] = 0ull; }
#pragma unroll 2
            for (int k = 0; k < NS; k++) {
                ulonglong2 v = *(const ulonglong2*)&rvs[k][lane * 4];
#pragma unroll
                for (int j = 0; j < 8; j++) {
                    u64 pp = pack2(lg[tok0 + j][k], lg[tok0 + j][k]);
                    fma2(o2[j][0], pp, v.x);
                    fma2(o2[j][1], pp, v.y);
                }
            }
#pragma unroll
            for (int j = 0; j < 8; j++) {
                float2 lo = unpk2(o2[j][0]), hi = unpk2(o2[j][1]);
                *(float4*)&Ob[(size_t)(tok0 + j) * DM + e0 + lane * 4] =
                    make_float4(lo.x, lo.y, hi.x, hi.y);
            }
        }
        __syncthreads();
    }
}

// ----------------- softmax over rows of 4096 (in place, smem row) -------------
__global__ __launch_bounds__(256) void kernel_softmax(float* __restrict__ attn)
{
    __shared__ __align__(16) float row[L_SZ];
    __shared__ float red[256];
    float* p = attn + (size_t)blockIdx.x * L_SZ;
    const int t = threadIdx.x;

    float m = -1e30f;
#pragma unroll
    for (int i = t * 4; i < L_SZ; i += 1024) {
        float4 v = *(const float4*)(p + i);
        *(float4*)&row[i] = v;
        m = fmaxf(m, fmaxf(fmaxf(v.x, v.y), fmaxf(v.z, v.w)));
    }
    red[t] = m; __syncthreads();
    for (int s = 128; s > 0; s >>= 1) { if (t < s) red[t] = fmaxf(red[t], red[t + s]); __syncthreads(); }
    m = red[0]; __syncthreads();

    float sum = 0.f;
#pragma unroll
    for (int i = t * 4; i < L_SZ; i += 1024) {
        float4 v = *(const float4*)&row[i];
        v.x = __expf(v.x - m); v.y = __expf(v.y - m);
        v.z = __expf(v.z - m); v.w = __expf(v.w - m);
        *(float4*)&row[i] = v;
        sum += v.x + v.y + v.z + v.w;
    }
    red[t] = sum; __syncthreads();
    for (int s = 128; s > 0; s >>= 1) { if (t < s) red[t] += red[t + s]; __syncthreads(); }
    const float inv = 1.f / red[0];
    __syncthreads();
#pragma unroll
    for (int i = t * 4; i < L_SZ; i += 1024) {
        float4 v = *(const float4*)&row[i];
        *(float4*)(p + i) = make_float4(v.x * inv, v.y * inv, v.z * inv, v.w * inv);
    }
}

// ------------------- T = attn @ H  (partials over NZ l chunks, f32x2) ---------
// 8-row unroll: 8 LDG.128 in flight per warp iteration.
__global__ __launch_bounds__(256) void kernel_attnH(
    const float* __restrict__ attn, const float* __restrict__ H)
{
    __shared__ __align__(16) float as[32][132];
    const int b = blockIdx.y, e0 = blockIdx.x * 128, z = blockIdx.z;
    const int t = threadIdx.x, lane = t & 31, wg = t >> 5;

    u64 acc2[4][2];
#pragma unroll
    for (int i = 0; i < 4; i++) { acc2[i][0] = 0ull; acc2[i][1] = 0ull; }

    const float* Ab = attn + (size_t)b * NS * L_SZ;
    const float* Hb = H + (size_t)b * L_SZ * DM + e0 + lane * 4;
    const int lbeg = z * (L_SZ / NZ);

    for (int l0 = lbeg; l0 < lbeg + (L_SZ / NZ); l0 += 128) {
        __syncthreads();
#pragma unroll
        for (int it = 0; it < 4; it++) {
            int idx = t + it * 256;           // 1024 float4 slots
            int s = idx >> 5, c = (idx & 31) << 2;
            *(float4*)&as[s][c] = *(const float4*)&Ab[(size_t)s * L_SZ + l0 + c];
        }
        __syncthreads();
#pragma unroll 2
        for (int l = 0; l < 128; l += 8) {
            ulonglong2 h2[8];
#pragma unroll
            for (int j = 0; j < 8; j++)
                h2[j] = *(const ulonglong2*)&Hb[(size_t)(l0 + l + j) * DM];
#pragma unroll
            for (int i = 0; i < 4; i++) {
                float4 a  = *(const float4*)&as[wg * 4 + i][l];
                float4 a2 = *(const float4*)&as[wg * 4 + i][l + 4];
                u64 p0 = pack2(a.x, a.x),  p1 = pack2(a.y, a.y);
                u64 p2 = pack2(a.z, a.z),  p3 = pack2(a.w, a.w);
                u64 p4 = pack2(a2.x, a2.x), p5 = pack2(a2.y, a2.y);
                u64 p6 = pack2(a2.z, a2.z), p7 = pack2(a2.w, a2.w);
                fma2(acc2[i][0], p0, h2[0].x); fma2(acc2[i][1], p0, h2[0].y);
                fma2(acc2[i][0], p1, h2[1].x); fma2(acc2[i][1], p1, h2[1].y);
                fma2(acc2[i][0], p2, h2[2].x); fma2(acc2[i][1], p2, h2[2].y);
                fma2(acc2[i][0], p3, h2[3].x); fma2(acc2[i][1], p3, h2[3].y);
                fma2(acc2[i][0], p4, h2[4].x); fma2(acc2[i][1], p4, h2[4].y);
                fma2(acc2[i][0], p5, h2[5].x); fma2(acc2[i][1], p5, h2[5].y);
                fma2(acc2[i][0], p6, h2[6].x); fma2(acc2[i][1], p6, h2[6].y);
                fma2(acc2[i][0], p7, h2[7].x); fma2(acc2[i][1], p7, h2[7].y);
            }
        }
    }
#pragma unroll
    for (int i = 0; i < 4; i++) {
        float2 lo = unpk2(acc2[i][0]), hi = unpk2(acc2[i][1]);
        *(float4*)&g_Tp[z][((size_t)b * NS + wg * 4 + i) * DM + e0 + lane * 4] =
            make_float4(lo.x, lo.y, hi.x, hi.y);
    }
}

__global__ void kernel_reduceT()
{
    const int i = blockIdx.x * 256 + threadIdx.x;
    if (i < B_SZ * NS * DM) {
        float s = 0.f;
#pragma unroll
        for (int z = 0; z < NZ; z++) s += g_Tp[z][i];
        g_T[i] = s;
    }
}

// ------------------------------- launcher -------------------------------------
extern "C" void kernel_launch(void* const* d_in, const int* in_sizes, int n_in,
                              void* d_out, int out_size)
{
    const float* H     = (const float*)d_in[0];
    // d_in[1] = mask (all true) — unused
    const float* slots = (const float*)d_in[2];
    const float* Wq    = (const float*)d_in[3];
    const float* Wk    = (const float*)d_in[4];
    const float* Wv    = (const float*)d_in[5];
    const float* Wrq   = (const float*)d_in[6];
    const float* Wrk   = (const float*)d_in[7];
    const float* Wrv   = (const float*)d_in[8];

    float* out      = (float*)d_out;
    float* out_Hhat = out;
    float* out_attn = out + OFF_ATTN;
    float* out_S    = out + OFF_S;

    float *pT, *pWcat, *prk2, *prv;
    cudaGetSymbolAddress((void**)&pT,    g_T);
    cudaGetSymbolAddress((void**)&pWcat, g_Wcat);
    cudaGetSymbolAddress((void**)&prk2,  g_rk2);
    cudaGetSymbolAddress((void**)&prv,   g_rv);

    // tiny precomputes
    kernel_q<<<NS, 256>>>(slots, Wq);
    kernel_qh<<<dim3(DM / 128, NS), 128>>>(Wk);
    kernel_mrr<<<dim3(DM / 64, DM / 64), 256>>>(Wrq, Wrk);
    // Wrv -> upper half of g_Wcat (D2D async copy, graph-capturable)
    cudaMemcpyAsync(pWcat + (size_t)DM * DM, Wrv, (size_t)DM * DM * sizeof(float),
                    cudaMemcpyDeviceToDevice, 0);

    // pass1: logits + softmax -> attn (output)
    kernel_logits2<<<dim3(L_SZ / 128, B_SZ), 128>>>(H, out_attn);
    kernel_softmax<<<B_SZ * NS, 256>>>(out_attn);

    // pass2: T = attn @ H
    kernel_attnH<<<dim3(DM / 128, B_SZ, NZ), 256>>>(out_attn, H);
    kernel_reduceT<<<(B_SZ * NS * DM + 255) / 256, 256>>>();

    // small GEMMs: S = T@Wv^T (output), then [rk2|rv] = S @ Wcat^T (fused)
    gemm64<<<dim3(DM / 64, (B_SZ * NS) / 64), 256>>>(pT, Wv, out_S, B_SZ * NS, DM, DM);
    gemm_cat<<<dim3(2 * DM / 64, (B_SZ * NS) / 64), 256>>>(out_S, prk2, prv);

    // pass3: fused recon logits + softmax + mix -> H_hat (output)
    kernel_recon_full<<<dim3(L_SZ / 128, B_SZ), 128>>>(H, out_Hhat);
}

// round 17
// speedup vs baseline: 1.5289x; 1.0260x over previous
#include <cuda_runtime.h>
#include <cuda_bf16.h>
#include <math.h>
#include <stdint.h>

// Problem constants
#define B_SZ 16
#define L_SZ 4096
#define DM 768
#define NS 32
#define DP 256
#define SCALE 0.0625f  // DP^-0.5 = 1/16

// Output layout: H_hat [B,L,DM] | attn [B,NS,L] | S [B,NS,DM]
#define OFF_ATTN (50331648)             // 16*4096*768
#define OFF_S    (50331648 + 2097152)   // + 16*32*4096

#define NZ 8   // l-split for attnH

typedef unsigned long long u64;

// ---------------------------- f32x2 helpers -----------------------------------
__device__ __forceinline__ u64 pack2(float lo, float hi) {
    u64 r;
    asm("mov.b64 %0, {%1, %2};" : "=l"(r) : "f"(lo), "f"(hi));
    return r;
}
__device__ __forceinline__ void fma2(u64& acc, u64 a, u64 b) {
    asm("fma.rn.f32x2 %0, %1, %2, %0;" : "+l"(acc) : "l"(a), "l"(b));
}
__device__ __forceinline__ float2 unpk2(u64 v) {
    float2 f;
    asm("mov.b64 {%0, %1}, %2;" : "=f"(f.x), "=f"(f.y) : "l"(v));
    return f;
}
__device__ __forceinline__ float red2(u64 v) { float2 f = unpk2(v); return f.x + f.y; }

// ---------------------------- cp.async helpers --------------------------------
__device__ __forceinline__ void cpa16(void* dst_smem, const void* src_gmem) {
    unsigned int d = (unsigned int)__cvta_generic_to_shared(dst_smem);
    asm volatile("cp.async.ca.shared.global [%0], [%1], 16;" :: "r"(d), "l"(src_gmem));
}
#define CPA_COMMIT() asm volatile("cp.async.commit_group;")
#define CPA_WAIT1()  asm volatile("cp.async.wait_group 1;")
#define CPA_WAIT0()  asm volatile("cp.async.wait_group 0;")

// ------------------------- scratch (no allocs allowed) -------------------------
__device__ __align__(16) float g_Q    [NS * DP];             // scale * slots @ Wq^T
__device__ __align__(16) float g_Qh   [NS * DM];             // g_Q @ Wk  (scale folded)
__device__ __align__(16) float g_Wcat [2 * DM * DM];         // rows 0..767: scale*Wrq^T@Wrk; 768..1535: Wrv
__device__ __align__(16) float g_Tp   [NZ][B_SZ * NS * DM];  // partial attn@H
__device__ __align__(16) float g_T    [B_SZ * NS * DM];      // attn@H
__device__ __align__(16) float g_rk2  [B_SZ * NS * DM];      // S @ Mrr^T
__device__ __align__(16) float g_rv   [B_SZ * NS * DM];      // S @ Wrv^T

// ------------------- Q = scale * slots @ Wq^T  [32,256] -----------------------
__global__ void kernel_q(const float* __restrict__ slots, const float* __restrict__ Wq)
{
    __shared__ float s[DM];
    const int k = blockIdx.x;
    const int t = threadIdx.x; // 256
    for (int i = t; i < DM; i += 256) s[i] = slots[k * DM + i];
    __syncthreads();
    const float* w = Wq + (size_t)t * DM;
    float acc = 0.f;
#pragma unroll 4
    for (int d = 0; d < DM; d += 4) {
        float4 wv = *(const float4*)(w + d);
        acc += s[d] * wv.x + s[d + 1] * wv.y + s[d + 2] * wv.z + s[d + 3] * wv.w;
    }
    g_Q[k * DP + t] = acc * SCALE;
}

// ------------------- Qh[k,d] = sum_p Q[k,p] * Wk[p,d]  [32,768] ---------------
__global__ __launch_bounds__(128) void kernel_qh(const float* __restrict__ Wk)
{
    __shared__ float Qk[DP];
    const int k = blockIdx.y;
    const int d = blockIdx.x * 128 + threadIdx.x;
    for (int i = threadIdx.x; i < DP; i += 128) Qk[i] = g_Q[k * DP + i];
    __syncthreads();
    float acc = 0.f;
#pragma unroll 4
    for (int p = 0; p < DP; p++) acc += Qk[p] * Wk[(size_t)p * DM + d];
    g_Qh[k * DM + d] = acc;
}

// -------- Mrr[d,e] = scale * sum_p Wrq[p,d]*Wrk[p,e] -> g_Wcat rows 0..767 ----
// register-prefetch pipelined over p-chunks of 16
__global__ __launch_bounds__(256) void kernel_mrr(
    const float* __restrict__ Wrq, const float* __restrict__ Wrk)
{
    __shared__ __align__(16) float As[16][68];
    __shared__ __align__(16) float Bs[16][68];
    const int t = threadIdx.x;
    const int d0 = blockIdx.y * 64, e0 = blockIdx.x * 64;
    const int tx = t & 15, ty = t >> 4;
    const int lr = t >> 2, lc = (t & 3) << 2;   // 64 rows x 16 cols loader map

    u64 acc2[4][2];
#pragma unroll
    for (int i = 0; i < 4; i++) { acc2[i][0] = 0ull; acc2[i][1] = 0ull; }

    // loader: thread loads Wrq[p0+lc.. p0+lc+3][d0+lr] column-wise? keep original
    // original loader: 4 iters of 256 covering 16x64. Prefetch into regs.
    float a_reg[4], b_reg[4];
#pragma unroll
    for (int it = 0; it < 4; it++) {
        int i = t + it * 256;
        int r = i >> 6, c = i & 63;
        a_reg[it] = Wrq[(size_t)r * DM + d0 + c];
        b_reg[it] = Wrk[(size_t)r * DM + e0 + c];
    }

    for (int p0 = 0; p0 < DP; p0 += 16) {
        __syncthreads();
#pragma unroll
        for (int it = 0; it < 4; it++) {
            int i = t + it * 256;
            int r = i >> 6, c = i & 63;
            As[r][c] = a_reg[it];
            Bs[r][c] = b_reg[it];
        }
        __syncthreads();
        if (p0 + 16 < DP) {
#pragma unroll
            for (int it = 0; it < 4; it++) {
                int i = t + it * 256;
                int r = (i >> 6) + p0 + 16, c = i & 63;
                a_reg[it] = Wrq[(size_t)r * DM + d0 + c];
                b_reg[it] = Wrk[(size_t)r * DM + e0 + c];
            }
        }
#pragma unroll
        for (int p = 0; p < 16; p++) {
            float4 a = *(const float4*)&As[p][ty * 4];
            ulonglong2 bv = *(const ulonglong2*)&Bs[p][tx * 4];
            u64 a0 = pack2(a.x, a.x), a1 = pack2(a.y, a.y);
            u64 a2 = pack2(a.z, a.z), a3 = pack2(a.w, a.w);
            fma2(acc2[0][0], a0, bv.x); fma2(acc2[0][1], a0, bv.y);
            fma2(acc2[1][0], a1, bv.x); fma2(acc2[1][1], a1, bv.y);
            fma2(acc2[2][0], a2, bv.x); fma2(acc2[2][1], a2, bv.y);
            fma2(acc2[3][0], a3, bv.x); fma2(acc2[3][1], a3, bv.y);
        }
    }
    (void)lr; (void)lc;
#pragma unroll
    for (int i = 0; i < 4; i++) {
        float2 lo = unpk2(acc2[i][0]), hi = unpk2(acc2[i][1]);
        float* c = g_Wcat + (size_t)(d0 + ty * 4 + i) * DM + e0 + tx * 4;
        *(float4*)c = make_float4(lo.x * SCALE, lo.y * SCALE, hi.x * SCALE, hi.y * SCALE);
    }
}

// ---------------- 64x64 TN GEMM: C[M,N] = A[M,K] . B[N,K]^T (f32x2) -----------
// register-prefetch pipelined: LDG for chunk k+1 issued before compute of k.
__global__ __launch_bounds__(256) void gemm64(
    const float* __restrict__ A, const float* __restrict__ Bm,
    float* __restrict__ C, int M, int N, int K)
{
    __shared__ __align__(16) float As[16][68];
    __shared__ __align__(16) float Bs[16][68];
    const int t = threadIdx.x;
    const int bm = blockIdx.y * 64, bn = blockIdx.x * 64;
    const int lr = t >> 2;            // 0..63
    const int lk = (t & 3) << 2;      // 0,4,8,12
    const int tx = t & 15, ty = t >> 4;

    u64 acc2[4][2];
#pragma unroll
    for (int i = 0; i < 4; i++) { acc2[i][0] = 0ull; acc2[i][1] = 0ull; }

    const float* Ap = A + (size_t)(bm + lr) * K + lk;
    const float* Bp = Bm + (size_t)(bn + lr) * K + lk;

    float4 a_reg = *(const float4*)(Ap);
    float4 b_reg = *(const float4*)(Bp);

    for (int k0 = 0; k0 < K; k0 += 16) {
        __syncthreads();
        As[lk + 0][lr] = a_reg.x; As[lk + 1][lr] = a_reg.y;
        As[lk + 2][lr] = a_reg.z; As[lk + 3][lr] = a_reg.w;
        Bs[lk + 0][lr] = b_reg.x; Bs[lk + 1][lr] = b_reg.y;
        Bs[lk + 2][lr] = b_reg.z; Bs[lk + 3][lr] = b_reg.w;
        __syncthreads();
        if (k0 + 16 < K) {
            a_reg = *(const float4*)(Ap + k0 + 16);
            b_reg = *(const float4*)(Bp + k0 + 16);
        }
#pragma unroll
        for (int kk = 0; kk < 16; kk++) {
            float4 av = *(const float4*)&As[kk][ty * 4];
            ulonglong2 bv = *(const ulonglong2*)&Bs[kk][tx * 4];
            u64 a0 = pack2(av.x, av.x), a1 = pack2(av.y, av.y);
            u64 a2 = pack2(av.z, av.z), a3 = pack2(av.w, av.w);
            fma2(acc2[0][0], a0, bv.x); fma2(acc2[0][1], a0, bv.y);
            fma2(acc2[1][0], a1, bv.x); fma2(acc2[1][1], a1, bv.y);
            fma2(acc2[2][0], a2, bv.x); fma2(acc2[2][1], a2, bv.y);
            fma2(acc2[3][0], a3, bv.x); fma2(acc2[3][1], a3, bv.y);
        }
    }
#pragma unroll
    for (int i = 0; i < 4; i++) {
        float2 lo = unpk2(acc2[i][0]), hi = unpk2(acc2[i][1]);
        float* c = C + (size_t)(bm + ty * 4 + i) * N + bn + tx * 4;
        *(float4*)c = make_float4(lo.x, lo.y, hi.x, hi.y);
    }
}

// ---- fused dual GEMM: [rk2 | rv] = S @ g_Wcat^T  (N = 1536, split output) ----
// register-prefetch pipelined.
__global__ __launch_bounds__(256) void gemm_cat(
    const float* __restrict__ A, float* __restrict__ C1, float* __restrict__ C2)
{
    __shared__ __align__(16) float As[16][68];
    __shared__ __align__(16) float Bs[16][68];
    const int t = threadIdx.x;
    const int bm = blockIdx.y * 64, bn = blockIdx.x * 64;
    const int lr = t >> 2, lk = (t & 3) << 2;
    const int tx = t & 15, ty = t >> 4;

    u64 acc2[4][2];
#pragma unroll
    for (int i = 0; i < 4; i++) { acc2[i][0] = 0ull; acc2[i][1] = 0ull; }

    const float* Ap = A + (size_t)(bm + lr) * DM + lk;
    const float* Bp = g_Wcat + (size_t)(bn + lr) * DM + lk;

    float4 a_reg = *(const float4*)(Ap);
    float4 b_reg = *(const float4*)(Bp);

    for (int k0 = 0; k0 < DM; k0 += 16) {
        __syncthreads();
        As[lk + 0][lr] = a_reg.x; As[lk + 1][lr] = a_reg.y;
        As[lk + 2][lr] = a_reg.z; As[lk + 3][lr] = a_reg.w;
        Bs[lk + 0][lr] = b_reg.x; Bs[lk + 1][lr] = b_reg.y;
        Bs[lk + 2][lr] = b_reg.z; Bs[lk + 3][lr] = b_reg.w;
        __syncthreads();
        if (k0 + 16 < DM) {
            a_reg = *(const float4*)(Ap + k0 + 16);
            b_reg = *(const float4*)(Bp + k0 + 16);
        }
#pragma unroll
        for (int kk = 0; kk < 16; kk++) {
            float4 av = *(const float4*)&As[kk][ty * 4];
            ulonglong2 bv = *(const ulonglong2*)&Bs[kk][tx * 4];
            u64 a0 = pack2(av.x, av.x), a1 = pack2(av.y, av.y);
            u64 a2 = pack2(av.z, av.z), a3 = pack2(av.w, av.w);
            fma2(acc2[0][0], a0, bv.x); fma2(acc2[0][1], a0, bv.y);
            fma2(acc2[1][0], a1, bv.x); fma2(acc2[1][1], a1, bv.y);
            fma2(acc2[2][0], a2, bv.x); fma2(acc2[2][1], a2, bv.y);
            fma2(acc2[3][0], a3, bv.x); fma2(acc2[3][1], a3, bv.y);
        }
    }
    float* Cd = (bn < DM) ? C1 : C2;
    const int cn = (bn < DM) ? bn : bn - DM;
#pragma unroll
    for (int i = 0; i < 4; i++) {
        float2 lo = unpk2(acc2[i][0]), hi = unpk2(acc2[i][1]);
        float* c = Cd + (size_t)(bm + ty * 4 + i) * DM + cn + tx * 4;
        *(float4*)c = make_float4(lo.x, lo.y, hi.x, hi.y);
    }
}

// ---- streaming logits: 128 threads, 128 tok x 32 slots, 4tok x 8slot/thread --
// 2-stage cp.async pipeline over d-chunks of 32.
#define DCH 32
#define NCH (DM / DCH)   // 24

__global__ __launch_bounds__(128) void kernel_logits2(
    const float* __restrict__ H, float* __restrict__ attn_out)
{
    __shared__ __align__(16) float Hs[2][128][36];
    __shared__ __align__(16) float Qs[2][32][36];
    const int b = blockIdx.y, l0 = blockIdx.x * 128;
    const int t = threadIdx.x;
    const int lane = t & 31, wg = t >> 5;
    const float* Hb = H + ((size_t)b * L_SZ + l0) * DM;

    u64 acc2[4][8];
#pragma unroll
    for (int j = 0; j < 4; j++)
#pragma unroll
        for (int s = 0; s < 8; s++) acc2[j][s] = 0ull;

    auto load_chunk = [&](int ch) {
        const int buf = ch & 1;
        const int d0 = ch * DCH;
#pragma unroll
        for (int it = 0; it < 8; it++) {
            int idx = t + it * 128;
            int r = idx >> 3, c = (idx & 7) << 2;
            cpa16(&Hs[buf][r][c], &Hb[(size_t)r * DM + d0 + c]);
        }
#pragma unroll
        for (int it = 0; it < 2; it++) {
            int idx = t + it * 128;
            int r = idx >> 3, c = (idx & 7) << 2;
            cpa16(&Qs[buf][r][c], &g_Qh[(size_t)r * DM + d0 + c]);
        }
        CPA_COMMIT();
    };

    load_chunk(0);
    for (int ch = 0; ch < NCH; ch++) {
        if (ch + 1 < NCH) { load_chunk(ch + 1); CPA_WAIT1(); }
        else              { CPA_WAIT0(); }
        __syncthreads();
        const int buf = ch & 1;
#pragma unroll
        for (int d = 0; d < DCH; d += 4) {
            ulonglong2 h2[4];
#pragma unroll
            for (int j = 0; j < 4; j++) h2[j] = *(const ulonglong2*)&Hs[buf][lane + 32 * j][d];
#pragma unroll
            for (int s = 0; s < 8; s++) {
                ulonglong2 q2 = *(const ulonglong2*)&Qs[buf][wg * 8 + s][d];
#pragma unroll
                for (int j = 0; j < 4; j++) {
                    fma2(acc2[j][s], h2[j].x, q2.x);
                    fma2(acc2[j][s], h2[j].y, q2.y);
                }
            }
        }
        __syncthreads();
    }
#pragma unroll
    for (int s = 0; s < 8; s++)
#pragma unroll
        for (int j = 0; j < 4; j++)
            attn_out[((size_t)(b * NS + wg * 8 + s)) * L_SZ + l0 + lane + 32 * j] = red2(acc2[j][s]);
}

// ---- fused recon: logits (H . rk2) -> per-token softmax(32) -> mix with rv ---
// 128 threads, 128 tokens per block. Same streaming pipeline; smem reused.
__global__ __launch_bounds__(128) void kernel_recon_full(
    const float* __restrict__ H, float* __restrict__ Hhat)
{
    __shared__ __align__(16) float Hs[2][128][36];
    __shared__ __align__(16) float Qs[2][32][36];
    const int b = blockIdx.y, l0 = blockIdx.x * 128;
    const int t = threadIdx.x;
    const int lane = t & 31, wg = t >> 5;
    const float* Hb = H + ((size_t)b * L_SZ + l0) * DM;
    const float* Bmat = g_rk2 + (size_t)b * NS * DM;

    u64 acc2[4][8];
#pragma unroll
    for (int j = 0; j < 4; j++)
#pragma unroll
        for (int s = 0; s < 8; s++) acc2[j][s] = 0ull;

    auto load_chunk = [&](int ch) {
        const int buf = ch & 1;
        const int d0 = ch * DCH;
#pragma unroll
        for (int it = 0; it < 8; it++) {
            int idx = t + it * 128;
            int r = idx >> 3, c = (idx & 7) << 2;
            cpa16(&Hs[buf][r][c], &Hb[(size_t)r * DM + d0 + c]);
        }
#pragma unroll
        for (int it = 0; it < 2; it++) {
            int idx = t + it * 128;
            int r = idx >> 3, c = (idx & 7) << 2;
            cpa16(&Qs[buf][r][c], &Bmat[(size_t)r * DM + d0 + c]);
        }
        CPA_COMMIT();
    };

    load_chunk(0);
    for (int ch = 0; ch < NCH; ch++) {
        if (ch + 1 < NCH) { load_chunk(ch + 1); CPA_WAIT1(); }
        else              { CPA_WAIT0(); }
        __syncthreads();
        const int buf = ch & 1;
#pragma unroll
        for (int d = 0; d < DCH; d += 4) {
            ulonglong2 h2[4];
#pragma unroll
            for (int j = 0; j < 4; j++) h2[j] = *(const ulonglong2*)&Hs[buf][lane + 32 * j][d];
#pragma unroll
            for (int s = 0; s < 8; s++) {
                ulonglong2 q2 = *(const ulonglong2*)&Qs[buf][wg * 8 + s][d];
#pragma unroll
                for (int j = 0; j < 4; j++) {
                    fma2(acc2[j][s], h2[j].x, q2.x);
                    fma2(acc2[j][s], h2[j].y, q2.y);
                }
            }
        }
        __syncthreads();
    }

    // lg[128][33] and rvs[32][132] alias the (now dead) Hs double buffer.
    // 128*33 + 32*132 = 8448 floats <= 2*128*36 = 9216 floats.
    float (*lg)[33]   = (float(*)[33])(&Hs[0][0][0]);
    float (*rvs)[132] = (float(*)[132])((float*)Hs + 128 * 33);

#pragma unroll
    for (int s = 0; s < 8; s++)
#pragma unroll
        for (int j = 0; j < 4; j++)
            lg[lane + 32 * j][wg * 8 + s] = red2(acc2[j][s]);
    __syncthreads();

    // per-token softmax over 32 slots (thread t <-> token t)
    {
        float m = -1e30f;
#pragma unroll
        for (int k = 0; k < NS; k++) m = fmaxf(m, lg[t][k]);
        float sum = 0.f;
#pragma unroll
        for (int k = 0; k < NS; k++) { float e = __expf(lg[t][k] - m); lg[t][k] = e; sum += e; }
        const float inv = 1.f / sum;
#pragma unroll
        for (int k = 0; k < NS; k++) lg[t][k] *= inv;
    }
    __syncthreads();

    // mix: H_hat[tok, e] = sum_k probs[tok][k] * rv[b,k,e]
    const float* rvb = g_rv + (size_t)b * NS * DM;
    float* Ob = Hhat + ((size_t)b * L_SZ + l0) * DM;

    for (int e0 = 0; e0 < DM; e0 += 128) {
#pragma unroll
        for (int it = 0; it < 8; it++) {
            int idx = t + it * 128;           // 1024 float4: 32 rows x 32 segs
            int r = idx >> 5, c = (idx & 31) << 2;
            *(float4*)&rvs[r][c] = *(const float4*)&rvb[(size_t)r * DM + e0 + c];
        }
        __syncthreads();
#pragma unroll
        for (int tg = 0; tg < 4; tg++) {
            const int tok0 = wg * 32 + tg * 8;
            u64 o2[8][2];
#pragma unroll
            for (int j = 0; j < 8; j++) { o2[j][0] = 0ull; o2[j][1] = 0ull; }
#pragma unroll 2
            for (int k = 0; k < NS; k++) {
                ulonglong2 v = *(const ulonglong2*)&rvs[k][lane * 4];
#pragma unroll
                for (int j = 0; j < 8; j++) {
                    u64 pp = pack2(lg[tok0 + j][k], lg[tok0 + j][k]);
                    fma2(o2[j][0], pp, v.x);
                    fma2(o2[j][1], pp, v.y);
                }
            }
#pragma unroll
            for (int j = 0; j < 8; j++) {
                float2 lo = unpk2(o2[j][0]), hi = unpk2(o2[j][1]);
                *(float4*)&Ob[(size_t)(tok0 + j) * DM + e0 + lane * 4] =
                    make_float4(lo.x, lo.y, hi.x, hi.y);
            }
        }
        __syncthreads();
    }
}

// ----------------- softmax over rows of 4096 (in place, smem row) -------------
__global__ __launch_bounds__(256) void kernel_softmax(float* __restrict__ attn)
{
    __shared__ __align__(16) float row[L_SZ];
    __shared__ float red[256];
    float* p = attn + (size_t)blockIdx.x * L_SZ;
    const int t = threadIdx.x;

    float m = -1e30f;
#pragma unroll
    for (int i = t * 4; i < L_SZ; i += 1024) {
        float4 v = *(const float4*)(p + i);
        *(float4*)&row[i] = v;
        m = fmaxf(m, fmaxf(fmaxf(v.x, v.y), fmaxf(v.z, v.w)));
    }
    red[t] = m; __syncthreads();
    for (int s = 128; s > 0; s >>= 1) { if (t < s) red[t] = fmaxf(red[t], red[t + s]); __syncthreads(); }
    m = red[0]; __syncthreads();

    float sum = 0.f;
#pragma unroll
    for (int i = t * 4; i < L_SZ; i += 1024) {
        float4 v = *(const float4*)&row[i];
        v.x = __expf(v.x - m); v.y = __expf(v.y - m);
        v.z = __expf(v.z - m); v.w = __expf(v.w - m);
        *(float4*)&row[i] = v;
        sum += v.x + v.y + v.z + v.w;
    }
    red[t] = sum; __syncthreads();
    for (int s = 128; s > 0; s >>= 1) { if (t < s) red[t] += red[t + s]; __syncthreads(); }
    const float inv = 1.f / red[0];
    __syncthreads();
#pragma unroll
    for (int i = t * 4; i < L_SZ; i += 1024) {
        float4 v = *(const float4*)&row[i];
        *(float4*)(p + i) = make_float4(v.x * inv, v.y * inv, v.z * inv, v.w * inv);
    }
}

// ------------------- T = attn @ H  (partials over NZ l chunks, f32x2) ---------
// 8-row unroll: 8 LDG.128 in flight per warp iteration.
__global__ __launch_bounds__(256) void kernel_attnH(
    const float* __restrict__ attn, const float* __restrict__ H)
{
    __shared__ __align__(16) float as[32][132];
    const int b = blockIdx.y, e0 = blockIdx.x * 128, z = blockIdx.z;
    const int t = threadIdx.x, lane = t & 31, wg = t >> 5;

    u64 acc2[4][2];
#pragma unroll
    for (int i = 0; i < 4; i++) { acc2[i][0] = 0ull; acc2[i][1] = 0ull; }

    const float* Ab = attn + (size_t)b * NS * L_SZ;
    const float* Hb = H + (size_t)b * L_SZ * DM + e0 + lane * 4;
    const int lbeg = z * (L_SZ / NZ);

    for (int l0 = lbeg; l0 < lbeg + (L_SZ / NZ); l0 += 128) {
        __syncthreads();
#pragma unroll
        for (int it = 0; it < 4; it++) {
            int idx = t + it * 256;           // 1024 float4 slots
            int s = idx >> 5, c = (idx & 31) << 2;
            *(float4*)&as[s][c] = *(const float4*)&Ab[(size_t)s * L_SZ + l0 + c];
        }
        __syncthreads();
#pragma unroll 2
        for (int l = 0; l < 128; l += 8) {
            ulonglong2 h2[8];
#pragma unroll
            for (int j = 0; j < 8; j++)
                h2[j] = *(const ulonglong2*)&Hb[(size_t)(l0 + l + j) * DM];
#pragma unroll
            for (int i = 0; i < 4; i++) {
                float4 a  = *(const float4*)&as[wg * 4 + i][l];
                float4 a2 = *(const float4*)&as[wg * 4 + i][l + 4];
                u64 p0 = pack2(a.x, a.x),  p1 = pack2(a.y, a.y);
                u64 p2 = pack2(a.z, a.z),  p3 = pack2(a.w, a.w);
                u64 p4 = pack2(a2.x, a2.x), p5 = pack2(a2.y, a2.y);
                u64 p6 = pack2(a2.z, a2.z), p7 = pack2(a2.w, a2.w);
                fma2(acc2[i][0], p0, h2[0].x); fma2(acc2[i][1], p0, h2[0].y);
                fma2(acc2[i][0], p1, h2[1].x); fma2(acc2[i][1], p1, h2[1].y);
                fma2(acc2[i][0], p2, h2[2].x); fma2(acc2[i][1], p2, h2[2].y);
                fma2(acc2[i][0], p3, h2[3].x); fma2(acc2[i][1], p3, h2[3].y);
                fma2(acc2[i][0], p4, h2[4].x); fma2(acc2[i][1], p4, h2[4].y);
                fma2(acc2[i][0], p5, h2[5].x); fma2(acc2[i][1], p5, h2[5].y);
                fma2(acc2[i][0], p6, h2[6].x); fma2(acc2[i][1], p6, h2[6].y);
                fma2(acc2[i][0], p7, h2[7].x); fma2(acc2[i][1], p7, h2[7].y);
            }
        }
    }
#pragma unroll
    for (int i = 0; i < 4; i++) {
        float2 lo = unpk2(acc2[i][0]), hi = unpk2(acc2[i][1]);
        *(float4*)&g_Tp[z][((size_t)b * NS + wg * 4 + i) * DM + e0 + lane * 4] =
            make_float4(lo.x, lo.y, hi.x, hi.y);
    }
}

__global__ void kernel_reduceT()
{
    const int i = blockIdx.x * 256 + threadIdx.x;
    if (i < B_SZ * NS * DM) {
        float s = 0.f;
#pragma unroll
        for (int z = 0; z < NZ; z++) s += g_Tp[z][i];
        g_T[i] = s;
    }
}

// ------------------------------- launcher -------------------------------------
extern "C" void kernel_launch(void* const* d_in, const int* in_sizes, int n_in,
                              void* d_out, int out_size)
{
    const float* H     = (const float*)d_in[0];
    // d_in[1] = mask (all true) — unused
    const float* slots = (const float*)d_in[2];
    const float* Wq    = (const float*)d_in[3];
    const float* Wk    = (const float*)d_in[4];
    const float* Wv    = (const float*)d_in[5];
    const float* Wrq   = (const float*)d_in[6];
    const float* Wrk   = (const float*)d_in[7];
    const float* Wrv   = (const float*)d_in[8];

    float* out      = (float*)d_out;
    float* out_Hhat = out;
    float* out_attn = out + OFF_ATTN;
    float* out_S    = out + OFF_S;

    float *pT, *pWcat, *prk2, *prv;
    cudaGetSymbolAddress((void**)&pT,    g_T);
    cudaGetSymbolAddress((void**)&pWcat, g_Wcat);
    cudaGetSymbolAddress((void**)&prk2,  g_rk2);
    cudaGetSymbolAddress((void**)&prv,   g_rv);

    // tiny precomputes
    kernel_q<<<NS, 256>>>(slots, Wq);
    kernel_qh<<<dim3(DM / 128, NS), 128>>>(Wk);
    kernel_mrr<<<dim3(DM / 64, DM / 64), 256>>>(Wrq, Wrk);
    // Wrv -> upper half of g_Wcat (D2D async copy, graph-capturable)
    cudaMemcpyAsync(pWcat + (size_t)DM * DM, Wrv, (size_t)DM * DM * sizeof(float),
                    cudaMemcpyDeviceToDevice, 0);

    // pass1: logits + softmax -> attn (output)
    kernel_logits2<<<dim3(L_SZ / 128, B_SZ), 128>>>(H, out_attn);
    kernel_softmax<<<B_SZ * NS, 256>>>(out_attn);

    // pass2: T = attn @ H
    kernel_attnH<<<dim3(DM / 128, B_SZ, NZ), 256>>>(out_attn, H);
    kernel_reduceT<<<(B_SZ * NS * DM + 255) / 256, 256>>>();

    // small GEMMs: S = T@Wv^T (output), then [rk2|rv] = S @ Wcat^T (fused)
    gemm64<<<dim3(DM / 64, (B_SZ * NS) / 64), 256>>>(pT, Wv, out_S, B_SZ * NS, DM, DM);
    gemm_cat<<<dim3(2 * DM / 64, (B_SZ * NS) / 64), 256>>>(out_S, prk2, prv);

    // pass3: fused recon logits + softmax + mix -> H_hat (output)
    kernel_recon_full<<<dim3(L_SZ / 128, B_SZ), 128>>>(H, out_Hhat);
}